// round 3
// baseline (speedup 1.0000x reference)
#include <cuda_runtime.h>
#include <cuda_fp16.h>

#define NN 50000
#define NE 1600000
#define TOT (NE + NN)
#define DIN 128
#define DH  64
#define BN_EPS 1e-5f

// ---------------- scratch ----------------
__device__ int   g_src[NE];
__device__ int   g_dst[NE];
__device__ float g_w[NE];
__device__ float g_deg[NN];
__device__ float g_dinv[NN];
__device__ int   g_cnt[NN];
__device__ int   g_cur[NN];
__device__ int   g_rowstart[NN + 1];
__device__ __align__(16) int2    g_cv[TOT];          // (col, norm-as-bits)
__device__ __align__(16) __half2 g_h[NN * (DH / 2)]; // fp16 features for gather
__device__ __align__(16) float   g_agg[NN * DH];     // fp32 aggregation output
__device__ float g_sum1[DH], g_sq1[DH], g_sum2[DH], g_sq2[DH];
__device__ int   g_is64 = 1;   // load-time init; probe only ever clears it (stable across replays)

// ---------------- f32x2 packed-FMA helpers (sm_10x FFMA2; PTX-only) ----------------
__device__ __forceinline__ unsigned long long bcast2(float x) {
    unsigned long long r; asm("mov.b64 %0, {%1,%1};" : "=l"(r) : "f"(x)); return r;
}
__device__ __forceinline__ void fma2(unsigned long long& d, unsigned long long a, unsigned long long b) {
    asm("fma.rn.f32x2 %0, %1, %2, %0;" : "+l"(d) : "l"(a), "l"(b));
}
__device__ __forceinline__ float2 unpack2(unsigned long long v) {
    float2 f; asm("mov.b64 {%0,%1}, %2;" : "=f"(f.x), "=f"(f.y) : "l"(v)); return f;
}

// ---------------- init + dtype probe ----------------
__global__ void k_init(const int* __restrict__ ei32) {
    int i = blockIdx.x * blockDim.x + threadIdx.x;
    if (i < NN) { g_deg[i] = 1.0f; g_cnt[i] = 1; g_cur[i] = 0; }
    if (i < DH) { g_sum1[i] = 0.f; g_sq1[i] = 0.f; g_sum2[i] = 0.f; g_sq2[i] = 0.f; }
    if (blockIdx.x == 0 && threadIdx.x < 256) {
        int k = threadIdx.x * (NE / 256);
        if (ei32[2 * k + 1] != 0) g_is64 = 0;   // int64 little-endian high word is 0
    }
}

// ---------------- edge prep: mix weights, degree, counts ----------------
__global__ void k_edge_prep(const void* __restrict__ ei,
                            const float* __restrict__ wsc,
                            const float* __restrict__ wfc,
                            const float* __restrict__ alpha) {
    int e = blockIdx.x * blockDim.x + threadIdx.x;
    if (e >= NE) return;
    float a = 1.f / (1.f + __expf(-__ldg(alpha)));
    int s, d;
    if (g_is64) {
        const long long* p = (const long long*)ei;
        s = (int)__ldg(&p[e]);
        d = (int)__ldg(&p[NE + e]);
    } else {
        const int* p = (const int*)ei;
        s = __ldg(&p[e]);
        d = __ldg(&p[NE + e]);
    }
    s = min(max(s, 0), NN - 1);
    d = min(max(d, 0), NN - 1);
    float w = a * __ldg(&wsc[e]) + (1.f - a) * __ldg(&wfc[e]);
    g_src[e] = s; g_dst[e] = d; g_w[e] = w;
    atomicAdd(&g_deg[d], w);
    atomicAdd(&g_cnt[d], 1);
}

// ---------------- single-block scan of g_cnt -> g_rowstart, fused dinv ----------------
#define SC_T 1024
#define SC_CH 49   // 1024*49 >= NN
__global__ void __launch_bounds__(SC_T) k_scan() {
    __shared__ int s[SC_T];
    int t = threadIdx.x;
    int b = t * SC_CH, e = min(b + SC_CH, NN);
    int sum = 0;
    for (int i = b; i < e; ++i) sum += g_cnt[i];
    s[t] = sum; __syncthreads();
    for (int off = 1; off < SC_T; off <<= 1) {
        int u = (t >= off) ? s[t - off] : 0;
        __syncthreads();
        s[t] += u; __syncthreads();
    }
    int pre = s[t] - sum;                      // exclusive prefix
    for (int i = b; i < e; ++i) {
        int c = g_cnt[i];
        g_rowstart[i] = pre; pre += c;
        g_dinv[i] = rsqrtf(g_deg[i]);          // deg >= 1 (self loop)
    }
    if (t == SC_T - 1) g_rowstart[NN] = TOT;
}

// ---------------- CSR fill: edges + self loops in one grid ----------------
__global__ void k_fill() {
    int e = blockIdx.x * blockDim.x + threadIdx.x;
    if (e < NE) {
        int d = g_dst[e], s = g_src[e];
        int p = g_rowstart[d] + atomicAdd(&g_cur[d], 1);
        float nv = g_dinv[s] * g_w[e] * g_dinv[d];
        g_cv[p] = make_int2(s, __float_as_int(nv));
    } else if (e < NE + NN) {
        int i = e - NE;
        int p = g_rowstart[i] + atomicAdd(&g_cur[i], 1);
        float di = g_dinv[i];
        g_cv[p] = make_int2(i, __float_as_int(di * di));
    }
}

// ---------------- GEMM1: g_h(fp16) = x[N,128] @ W1[128,64] ----------------
__global__ void __launch_bounds__(256) k_gemm1(const float* __restrict__ x,
                                               const float* __restrict__ W1) {
    __shared__ __align__(16) float sW[DIN * DH];      // 32 KB
    for (int i = threadIdx.x; i < DIN * DH; i += 256) sW[i] = W1[i];
    __syncthreads();
    int warp = threadIdx.x >> 5, lane = threadIdx.x & 31;
    int nbase = blockIdx.x * 32 + warp * 4;
    if (nbase >= NN) return;
    int n0 = nbase, n1 = min(nbase + 1, NN - 1), n2 = min(nbase + 2, NN - 1), n3 = min(nbase + 3, NN - 1);
    const float4* x0 = (const float4*)(x + (size_t)n0 * DIN);
    const float4* x1 = (const float4*)(x + (size_t)n1 * DIN);
    const float4* x2 = (const float4*)(x + (size_t)n2 * DIN);
    const float4* x3 = (const float4*)(x + (size_t)n3 * DIN);
    unsigned long long a0 = 0ULL, a1 = 0ULL, a2 = 0ULL, a3 = 0ULL;
    #pragma unroll
    for (int kk = 0; kk < DIN / 4; ++kk) {
        float ra[4], rb[4], rc[4], rd[4];
        *(float4*)ra = __ldg(x0 + kk);
        *(float4*)rb = __ldg(x1 + kk);
        *(float4*)rc = __ldg(x2 + kk);
        *(float4*)rd = __ldg(x3 + kk);
        #pragma unroll
        for (int u = 0; u < 4; ++u) {
            unsigned long long w = *(const unsigned long long*)&sW[(4 * kk + u) * DH + 2 * lane];
            fma2(a0, bcast2(ra[u]), w);
            fma2(a1, bcast2(rb[u]), w);
            fma2(a2, bcast2(rc[u]), w);
            fma2(a3, bcast2(rd[u]), w);
        }
    }
    g_h[(size_t)n0 * 32 + lane] = __float22half2_rn(unpack2(a0));
    if (nbase + 1 < NN) g_h[(size_t)n1 * 32 + lane] = __float22half2_rn(unpack2(a1));
    if (nbase + 2 < NN) g_h[(size_t)n2 * 32 + lane] = __float22half2_rn(unpack2(a2));
    if (nbase + 3 < NN) g_h[(size_t)n3 * 32 + lane] = __float22half2_rn(unpack2(a3));
}

// ---------------- CSR gather agg + bias, fused column stats ----------------
// grid = NN/8 blocks of 256 (one row per warp); NN % 8 == 0
__global__ void __launch_bounds__(256) k_agg(const float* __restrict__ bias,
                                             float* __restrict__ gsum,
                                             float* __restrict__ gsq) {
    __shared__ float s_sum[DH], s_sq[DH];
    if (threadIdx.x < DH) { s_sum[threadIdx.x] = 0.f; s_sq[threadIdx.x] = 0.f; }
    __syncthreads();
    int gw = blockIdx.x * 8 + (threadIdx.x >> 5);
    int lane = threadIdx.x & 31;
    int beg = g_rowstart[gw], end = g_rowstart[gw + 1];
    const __half2* hp = g_h;
    float2 acc = {0.f, 0.f};
    int j = beg;
    for (; j + 4 <= end; j += 4) {
        int2 c0 = g_cv[j], c1 = g_cv[j + 1], c2 = g_cv[j + 2], c3 = g_cv[j + 3];
        float2 h0 = __half22float2(__ldg(&hp[(size_t)c0.x * 32 + lane]));
        float2 h1 = __half22float2(__ldg(&hp[(size_t)c1.x * 32 + lane]));
        float2 h2 = __half22float2(__ldg(&hp[(size_t)c2.x * 32 + lane]));
        float2 h3 = __half22float2(__ldg(&hp[(size_t)c3.x * 32 + lane]));
        float v0 = __int_as_float(c0.y), v1 = __int_as_float(c1.y);
        float v2 = __int_as_float(c2.y), v3 = __int_as_float(c3.y);
        acc.x += v0 * h0.x; acc.y += v0 * h0.y;
        acc.x += v1 * h1.x; acc.y += v1 * h1.y;
        acc.x += v2 * h2.x; acc.y += v2 * h2.y;
        acc.x += v3 * h3.x; acc.y += v3 * h3.y;
    }
    for (; j < end; ++j) {
        int2 c = g_cv[j];
        float2 hv = __half22float2(__ldg(&hp[(size_t)c.x * 32 + lane]));
        float v = __int_as_float(c.y);
        acc.x += v * hv.x; acc.y += v * hv.y;
    }
    acc.x += __ldg(&bias[2 * lane]);
    acc.y += __ldg(&bias[2 * lane + 1]);
    *(float2*)&g_agg[(size_t)gw * DH + 2 * lane] = acc;
    // block-level stats then one global atomic per column
    atomicAdd(&s_sum[2 * lane],     acc.x);
    atomicAdd(&s_sum[2 * lane + 1], acc.y);
    atomicAdd(&s_sq[2 * lane],      acc.x * acc.x);
    atomicAdd(&s_sq[2 * lane + 1],  acc.y * acc.y);
    __syncthreads();
    if (threadIdx.x < DH) {
        atomicAdd(&gsum[threadIdx.x], s_sum[threadIdx.x]);
        atomicAdd(&gsq[threadIdx.x],  s_sq[threadIdx.x]);
    }
}

// ---------------- GEMM2: g_h(fp16) = relu(bn(g_agg)) @ W2[64,64]; BN params from stats ----------------
__global__ void __launch_bounds__(256) k_gemm2(const float* __restrict__ W2,
                                               const float* __restrict__ gamma,
                                               const float* __restrict__ beta) {
    __shared__ __align__(16) float sW[DH * DH];
    __shared__ __align__(16) float ssc[DH], ssh[DH];
    for (int i = threadIdx.x; i < DH * DH; i += 256) sW[i] = W2[i];
    if (threadIdx.x < DH) {
        int c = threadIdx.x;
        float mean = g_sum1[c] * (1.f / NN);
        float var  = g_sq1[c] * (1.f / NN) - mean * mean;
        float inv  = rsqrtf(var + BN_EPS);
        float sc   = __ldg(&gamma[c]) * inv;
        ssc[c] = sc;
        ssh[c] = __ldg(&beta[c]) - mean * sc;
    }
    __syncthreads();
    int warp = threadIdx.x >> 5, lane = threadIdx.x & 31;
    int nbase = blockIdx.x * 32 + warp * 4;
    if (nbase >= NN) return;
    int n0 = nbase, n1 = min(nbase + 1, NN - 1), n2 = min(nbase + 2, NN - 1), n3 = min(nbase + 3, NN - 1);
    const float4* x0 = (const float4*)(g_agg + (size_t)n0 * DH);
    const float4* x1 = (const float4*)(g_agg + (size_t)n1 * DH);
    const float4* x2 = (const float4*)(g_agg + (size_t)n2 * DH);
    const float4* x3 = (const float4*)(g_agg + (size_t)n3 * DH);
    unsigned long long a0 = 0ULL, a1 = 0ULL, a2 = 0ULL, a3 = 0ULL;
    #pragma unroll
    for (int kk = 0; kk < DH / 4; ++kk) {
        float ra[4], rb[4], rc[4], rd[4];
        *(float4*)ra = __ldg(x0 + kk);
        *(float4*)rb = __ldg(x1 + kk);
        *(float4*)rc = __ldg(x2 + kk);
        *(float4*)rd = __ldg(x3 + kk);
        float scs[4], shs[4];
        *(float4*)scs = *(float4*)&ssc[4 * kk];
        *(float4*)shs = *(float4*)&ssh[4 * kk];
        #pragma unroll
        for (int u = 0; u < 4; ++u) {
            unsigned long long w = *(const unsigned long long*)&sW[(4 * kk + u) * DH + 2 * lane];
            float va = fmaxf(fmaf(ra[u], scs[u], shs[u]), 0.f);
            float vb = fmaxf(fmaf(rb[u], scs[u], shs[u]), 0.f);
            float vc = fmaxf(fmaf(rc[u], scs[u], shs[u]), 0.f);
            float vd = fmaxf(fmaf(rd[u], scs[u], shs[u]), 0.f);
            fma2(a0, bcast2(va), w);
            fma2(a1, bcast2(vb), w);
            fma2(a2, bcast2(vc), w);
            fma2(a3, bcast2(vd), w);
        }
    }
    g_h[(size_t)n0 * 32 + lane] = __float22half2_rn(unpack2(a0));
    if (nbase + 1 < NN) g_h[(size_t)n1 * 32 + lane] = __float22half2_rn(unpack2(a1));
    if (nbase + 2 < NN) g_h[(size_t)n2 * 32 + lane] = __float22half2_rn(unpack2(a2));
    if (nbase + 3 < NN) g_h[(size_t)n3 * 32 + lane] = __float22half2_rn(unpack2(a3));
}

// ---------------- final: out = relu(bn(g_agg)); BN params from stats ----------------
__global__ void __launch_bounds__(256) k_final(const float* __restrict__ gamma,
                                               const float* __restrict__ beta,
                                               float* __restrict__ out) {
    __shared__ float ssc[DH], ssh[DH];
    if (threadIdx.x < DH) {
        int c = threadIdx.x;
        float mean = g_sum2[c] * (1.f / NN);
        float var  = g_sq2[c] * (1.f / NN) - mean * mean;
        float inv  = rsqrtf(var + BN_EPS);
        float sc   = __ldg(&gamma[c]) * inv;
        ssc[c] = sc;
        ssh[c] = __ldg(&beta[c]) - mean * sc;
    }
    __syncthreads();
    int idx = blockIdx.x * blockDim.x + threadIdx.x;   // over NN*16 float4s
    if (idx >= NN * (DH / 4)) return;
    float4 v = ((const float4*)g_agg)[idx];
    int cb = (idx & (DH / 4 - 1)) * 4;
    v.x = fmaxf(fmaf(v.x, ssc[cb + 0], ssh[cb + 0]), 0.f);
    v.y = fmaxf(fmaf(v.y, ssc[cb + 1], ssh[cb + 1]), 0.f);
    v.z = fmaxf(fmaf(v.z, ssc[cb + 2], ssh[cb + 2]), 0.f);
    v.w = fmaxf(fmaf(v.w, ssc[cb + 3], ssh[cb + 3]), 0.f);
    ((float4*)out)[idx] = v;
}

// ---------------- launch ----------------
extern "C" void kernel_launch(void* const* d_in, const int* in_sizes, int n_in,
                              void* d_out, int out_size) {
    const float* x      = (const float*)d_in[0];
    const void*  ei_sc  = d_in[1];
    const float* wsc    = (const float*)d_in[2];
    // d_in[3] = edge_index_fc (unused by the reference math)
    const float* wfc    = (const float*)d_in[4];
    const float* alpha  = (const float*)d_in[5];
    const float* W1     = (const float*)d_in[6];
    const float* b1     = (const float*)d_in[7];
    const float* W2     = (const float*)d_in[8];
    const float* b2     = (const float*)d_in[9];
    const float* gamma1 = (const float*)d_in[10];
    const float* beta1  = (const float*)d_in[11];
    const float* gamma2 = (const float*)d_in[12];
    const float* beta2  = (const float*)d_in[13];
    float*       out    = (float*)d_out;

    const int TB = 256;
    float* d_sum1; cudaGetSymbolAddress((void**)&d_sum1, g_sum1);
    float* d_sq1;  cudaGetSymbolAddress((void**)&d_sq1,  g_sq1);
    float* d_sum2; cudaGetSymbolAddress((void**)&d_sum2, g_sum2);
    float* d_sq2;  cudaGetSymbolAddress((void**)&d_sq2,  g_sq2);

    k_init<<<(NN + TB - 1) / TB, TB>>>((const int*)ei_sc);
    k_edge_prep<<<(NE + TB - 1) / TB, TB>>>(ei_sc, wsc, wfc, alpha);
    k_scan<<<1, SC_T>>>();
    k_fill<<<(NE + NN + TB - 1) / TB, TB>>>();
    k_gemm1<<<(NN + 31) / 32, TB>>>(x, W1);
    k_agg<<<NN / 8, TB>>>(b1, d_sum1, d_sq1);
    k_gemm2<<<(NN + 31) / 32, TB>>>(W2, gamma1, beta1);
    k_agg<<<NN / 8, TB>>>(b2, d_sum2, d_sq2);
    k_final<<<(NN * (DH / 4) + TB - 1) / TB, TB>>>(gamma2, beta2, out);
}

// round 4
// speedup vs baseline: 1.4632x; 1.4632x over previous
#include <cuda_runtime.h>
#include <cuda_fp16.h>

#define NN 50000
#define NE 1600000
#define TOT (NE + NN)
#define DIN 128
#define DH  64
#define SCAN_B 512
#define NB_SCAN 98   // ceil(NN/512)
#define BN_EPS 1e-5f

// ---------------- scratch ----------------
__device__ int   g_src[NE];
__device__ int   g_dst[NE];
__device__ float g_w[NE];
__device__ float g_deg[NN];
__device__ float g_dinv[NN];
__device__ int   g_cnt[NN];
__device__ int   g_cur[NN];
__device__ int   g_rowstart[NN + 1];
__device__ int   g_bsum[NB_SCAN];
__device__ __align__(16) int2    g_cv[TOT];          // (col, dinv[src]*w as bits)
__device__ __align__(16) __half2 g_h[NN * (DH / 2)]; // fp16 features for gather
__device__ __align__(16) float   g_agg[NN * DH];     // fp32 aggregation output
__device__ float g_sum1[DH], g_sq1[DH], g_sum2[DH], g_sq2[DH];
__device__ int   g_is64 = 1;   // probe only ever clears it (stable across replays)

// ---------------- f32x2 packed-FMA helpers (sm_10x FFMA2; PTX-only) ----------------
__device__ __forceinline__ unsigned long long bcast2(float x) {
    unsigned long long r; asm("mov.b64 %0, {%1,%1};" : "=l"(r) : "f"(x)); return r;
}
__device__ __forceinline__ void fma2(unsigned long long& d, unsigned long long a, unsigned long long b) {
    asm("fma.rn.f32x2 %0, %1, %2, %0;" : "+l"(d) : "l"(a), "l"(b));
}
__device__ __forceinline__ float2 unpack2(unsigned long long v) {
    float2 f; asm("mov.b64 {%0,%1}, %2;" : "=f"(f.x), "=f"(f.y) : "l"(v)); return f;
}

// ---------------- init + dtype probe ----------------
__global__ void k_init(const int* __restrict__ ei32) {
    int i = blockIdx.x * blockDim.x + threadIdx.x;
    if (i < NN) { g_deg[i] = 1.0f; g_cnt[i] = 1; g_cur[i] = 0; }
    if (i < DH) { g_sum1[i] = 0.f; g_sq1[i] = 0.f; g_sum2[i] = 0.f; g_sq2[i] = 0.f; }
    if (blockIdx.x == 0 && threadIdx.x < 256) {
        int k = threadIdx.x * (NE / 256);
        if (ei32[2 * k + 1] != 0) g_is64 = 0;   // int64 LE high word is 0
    }
}

// ---------------- edge prep: mix weights, degree, counts ----------------
__global__ void k_edge_prep(const void* __restrict__ ei,
                            const float* __restrict__ wsc,
                            const float* __restrict__ wfc,
                            const float* __restrict__ alpha) {
    int e = blockIdx.x * blockDim.x + threadIdx.x;
    if (e >= NE) return;
    float a = 1.f / (1.f + __expf(-__ldg(alpha)));
    int s, d;
    if (g_is64) {
        const long long* p = (const long long*)ei;
        s = (int)__ldg(&p[e]);
        d = (int)__ldg(&p[NE + e]);
    } else {
        const int* p = (const int*)ei;
        s = __ldg(&p[e]);
        d = __ldg(&p[NE + e]);
    }
    s = min(max(s, 0), NN - 1);
    d = min(max(d, 0), NN - 1);
    float w = a * __ldg(&wsc[e]) + (1.f - a) * __ldg(&wfc[e]);
    g_src[e] = s; g_dst[e] = d; g_w[e] = w;
    atomicAdd(&g_deg[d], w);
    atomicAdd(&g_cnt[d], 1);
}

// ---------------- hierarchical exclusive scan of g_cnt -> g_rowstart ----------------
__global__ void k_scan1() {
    __shared__ int s[SCAN_B];
    int t = threadIdx.x;
    int i = blockIdx.x * SCAN_B + t;
    int v = (i < NN) ? g_cnt[i] : 0;
    s[t] = v; __syncthreads();
    for (int off = 1; off < SCAN_B; off <<= 1) {
        int u = (t >= off) ? s[t - off] : 0;
        __syncthreads();
        s[t] += u; __syncthreads();
    }
    if (i < NN) g_rowstart[i] = s[t] - v;          // exclusive, pre-offset
    if (t == SCAN_B - 1) g_bsum[blockIdx.x] = s[t];
}
__global__ void k_scan2() {
    __shared__ int s[128];
    int t = threadIdx.x;
    int v = (t < NB_SCAN) ? g_bsum[t] : 0;
    s[t] = v; __syncthreads();
    for (int off = 1; off < 128; off <<= 1) {
        int u = (t >= off) ? s[t - off] : 0;
        __syncthreads();
        s[t] += u; __syncthreads();
    }
    if (t < NB_SCAN) g_bsum[t] = s[t] - v;         // exclusive block offsets
}
__global__ void k_scan3() {   // also computes dinv
    int i = blockIdx.x * SCAN_B + threadIdx.x;
    if (i < NN) {
        g_rowstart[i] += g_bsum[i >> 9];
        g_dinv[i] = rsqrtf(g_deg[i]);              // deg >= 1 (self loop)
    }
    if (i == 0) g_rowstart[NN] = TOT;
}

// ---------------- CSR fill: edges + self loops; value = dinv[src]*w (dst factor applied in agg) ----------------
__global__ void k_fill() {
    int e = blockIdx.x * blockDim.x + threadIdx.x;
    if (e < NE) {
        int d = g_dst[e], s = g_src[e];
        int p = g_rowstart[d] + atomicAdd(&g_cur[d], 1);
        float nv = g_dinv[s] * g_w[e];
        g_cv[p] = make_int2(s, __float_as_int(nv));
    } else if (e < NE + NN) {
        int i = e - NE;
        int p = g_rowstart[i] + atomicAdd(&g_cur[i], 1);
        g_cv[p] = make_int2(i, __float_as_int(g_dinv[i]));
    }
}

// ---------------- GEMM1: g_h(fp16) = x[N,128] @ W1[128,64] ----------------
__global__ void __launch_bounds__(256) k_gemm1(const float* __restrict__ x,
                                               const float* __restrict__ W1) {
    __shared__ __align__(16) float sW[DIN * DH];      // 32 KB
    for (int i = threadIdx.x; i < DIN * DH; i += 256) sW[i] = W1[i];
    __syncthreads();
    int warp = threadIdx.x >> 5, lane = threadIdx.x & 31;
    int nbase = blockIdx.x * 32 + warp * 4;
    if (nbase >= NN) return;
    int n0 = nbase, n1 = min(nbase + 1, NN - 1), n2 = min(nbase + 2, NN - 1), n3 = min(nbase + 3, NN - 1);
    const float4* x0 = (const float4*)(x + (size_t)n0 * DIN);
    const float4* x1 = (const float4*)(x + (size_t)n1 * DIN);
    const float4* x2 = (const float4*)(x + (size_t)n2 * DIN);
    const float4* x3 = (const float4*)(x + (size_t)n3 * DIN);
    unsigned long long a0 = 0ULL, a1 = 0ULL, a2 = 0ULL, a3 = 0ULL;
    #pragma unroll
    for (int kk = 0; kk < DIN / 4; ++kk) {
        float ra[4], rb[4], rc[4], rd[4];
        *(float4*)ra = __ldg(x0 + kk);
        *(float4*)rb = __ldg(x1 + kk);
        *(float4*)rc = __ldg(x2 + kk);
        *(float4*)rd = __ldg(x3 + kk);
        #pragma unroll
        for (int u = 0; u < 4; ++u) {
            unsigned long long w = *(const unsigned long long*)&sW[(4 * kk + u) * DH + 2 * lane];
            fma2(a0, bcast2(ra[u]), w);
            fma2(a1, bcast2(rb[u]), w);
            fma2(a2, bcast2(rc[u]), w);
            fma2(a3, bcast2(rd[u]), w);
        }
    }
    g_h[(size_t)n0 * 32 + lane] = __float22half2_rn(unpack2(a0));
    if (nbase + 1 < NN) g_h[(size_t)n1 * 32 + lane] = __float22half2_rn(unpack2(a1));
    if (nbase + 2 < NN) g_h[(size_t)n2 * 32 + lane] = __float22half2_rn(unpack2(a2));
    if (nbase + 3 < NN) g_h[(size_t)n3 * 32 + lane] = __float22half2_rn(unpack2(a3));
}

// ---------------- CSR gather agg (row scaled by dinv[dst]) + bias, fused column stats ----------------
__global__ void __launch_bounds__(256) k_agg(const float* __restrict__ bias,
                                             float* __restrict__ gsum,
                                             float* __restrict__ gsq) {
    __shared__ float s_sum[DH], s_sq[DH];
    if (threadIdx.x < DH) { s_sum[threadIdx.x] = 0.f; s_sq[threadIdx.x] = 0.f; }
    __syncthreads();
    int gw = blockIdx.x * 8 + (threadIdx.x >> 5);
    int lane = threadIdx.x & 31;
    int beg = g_rowstart[gw], end = g_rowstart[gw + 1];
    const __half2* hp = g_h;
    float2 acc = {0.f, 0.f};
    int j = beg;
    for (; j + 4 <= end; j += 4) {
        int2 c0 = g_cv[j], c1 = g_cv[j + 1], c2 = g_cv[j + 2], c3 = g_cv[j + 3];
        float2 h0 = __half22float2(__ldg(&hp[(size_t)c0.x * 32 + lane]));
        float2 h1 = __half22float2(__ldg(&hp[(size_t)c1.x * 32 + lane]));
        float2 h2 = __half22float2(__ldg(&hp[(size_t)c2.x * 32 + lane]));
        float2 h3 = __half22float2(__ldg(&hp[(size_t)c3.x * 32 + lane]));
        float v0 = __int_as_float(c0.y), v1 = __int_as_float(c1.y);
        float v2 = __int_as_float(c2.y), v3 = __int_as_float(c3.y);
        acc.x += v0 * h0.x; acc.y += v0 * h0.y;
        acc.x += v1 * h1.x; acc.y += v1 * h1.y;
        acc.x += v2 * h2.x; acc.y += v2 * h2.y;
        acc.x += v3 * h3.x; acc.y += v3 * h3.y;
    }
    for (; j < end; ++j) {
        int2 c = g_cv[j];
        float2 hv = __half22float2(__ldg(&hp[(size_t)c.x * 32 + lane]));
        float v = __int_as_float(c.y);
        acc.x += v * hv.x; acc.y += v * hv.y;
    }
    float di = g_dinv[gw];
    acc.x = acc.x * di + __ldg(&bias[2 * lane]);
    acc.y = acc.y * di + __ldg(&bias[2 * lane + 1]);
    *(float2*)&g_agg[(size_t)gw * DH + 2 * lane] = acc;
    // block-level stats then one global atomic per column
    atomicAdd(&s_sum[2 * lane],     acc.x);
    atomicAdd(&s_sum[2 * lane + 1], acc.y);
    atomicAdd(&s_sq[2 * lane],      acc.x * acc.x);
    atomicAdd(&s_sq[2 * lane + 1],  acc.y * acc.y);
    __syncthreads();
    if (threadIdx.x < DH) {
        atomicAdd(&gsum[threadIdx.x], s_sum[threadIdx.x]);
        atomicAdd(&gsq[threadIdx.x],  s_sq[threadIdx.x]);
    }
}

// ---------------- GEMM2: g_h(fp16) = relu(bn(g_agg)) @ W2[64,64]; BN params from stats ----------------
__global__ void __launch_bounds__(256) k_gemm2(const float* __restrict__ W2,
                                               const float* __restrict__ gamma,
                                               const float* __restrict__ beta) {
    __shared__ __align__(16) float sW[DH * DH];
    __shared__ __align__(16) float ssc[DH], ssh[DH];
    for (int i = threadIdx.x; i < DH * DH; i += 256) sW[i] = W2[i];
    if (threadIdx.x < DH) {
        int c = threadIdx.x;
        float mean = g_sum1[c] * (1.f / NN);
        float var  = g_sq1[c] * (1.f / NN) - mean * mean;
        float inv  = rsqrtf(var + BN_EPS);
        float sc   = __ldg(&gamma[c]) * inv;
        ssc[c] = sc;
        ssh[c] = __ldg(&beta[c]) - mean * sc;
    }
    __syncthreads();
    int warp = threadIdx.x >> 5, lane = threadIdx.x & 31;
    int nbase = blockIdx.x * 32 + warp * 4;
    if (nbase >= NN) return;
    int n0 = nbase, n1 = min(nbase + 1, NN - 1), n2 = min(nbase + 2, NN - 1), n3 = min(nbase + 3, NN - 1);
    const float4* x0 = (const float4*)(g_agg + (size_t)n0 * DH);
    const float4* x1 = (const float4*)(g_agg + (size_t)n1 * DH);
    const float4* x2 = (const float4*)(g_agg + (size_t)n2 * DH);
    const float4* x3 = (const float4*)(g_agg + (size_t)n3 * DH);
    unsigned long long a0 = 0ULL, a1 = 0ULL, a2 = 0ULL, a3 = 0ULL;
    #pragma unroll
    for (int kk = 0; kk < DH / 4; ++kk) {
        float ra[4], rb[4], rc[4], rd[4];
        *(float4*)ra = __ldg(x0 + kk);
        *(float4*)rb = __ldg(x1 + kk);
        *(float4*)rc = __ldg(x2 + kk);
        *(float4*)rd = __ldg(x3 + kk);
        float scs[4], shs[4];
        *(float4*)scs = *(float4*)&ssc[4 * kk];
        *(float4*)shs = *(float4*)&ssh[4 * kk];
        #pragma unroll
        for (int u = 0; u < 4; ++u) {
            unsigned long long w = *(const unsigned long long*)&sW[(4 * kk + u) * DH + 2 * lane];
            float va = fmaxf(fmaf(ra[u], scs[u], shs[u]), 0.f);
            float vb = fmaxf(fmaf(rb[u], scs[u], shs[u]), 0.f);
            float vc = fmaxf(fmaf(rc[u], scs[u], shs[u]), 0.f);
            float vd = fmaxf(fmaf(rd[u], scs[u], shs[u]), 0.f);
            fma2(a0, bcast2(va), w);
            fma2(a1, bcast2(vb), w);
            fma2(a2, bcast2(vc), w);
            fma2(a3, bcast2(vd), w);
        }
    }
    g_h[(size_t)n0 * 32 + lane] = __float22half2_rn(unpack2(a0));
    if (nbase + 1 < NN) g_h[(size_t)n1 * 32 + lane] = __float22half2_rn(unpack2(a1));
    if (nbase + 2 < NN) g_h[(size_t)n2 * 32 + lane] = __float22half2_rn(unpack2(a2));
    if (nbase + 3 < NN) g_h[(size_t)n3 * 32 + lane] = __float22half2_rn(unpack2(a3));
}

// ---------------- final: out = relu(bn(g_agg)); BN params from stats ----------------
__global__ void __launch_bounds__(256) k_final(const float* __restrict__ gamma,
                                               const float* __restrict__ beta,
                                               float* __restrict__ out) {
    __shared__ float ssc[DH], ssh[DH];
    if (threadIdx.x < DH) {
        int c = threadIdx.x;
        float mean = g_sum2[c] * (1.f / NN);
        float var  = g_sq2[c] * (1.f / NN) - mean * mean;
        float inv  = rsqrtf(var + BN_EPS);
        float sc   = __ldg(&gamma[c]) * inv;
        ssc[c] = sc;
        ssh[c] = __ldg(&beta[c]) - mean * sc;
    }
    __syncthreads();
    int idx = blockIdx.x * blockDim.x + threadIdx.x;   // over NN*16 float4s
    if (idx >= NN * (DH / 4)) return;
    float4 v = ((const float4*)g_agg)[idx];
    int cb = (idx & (DH / 4 - 1)) * 4;
    v.x = fmaxf(fmaf(v.x, ssc[cb + 0], ssh[cb + 0]), 0.f);
    v.y = fmaxf(fmaf(v.y, ssc[cb + 1], ssh[cb + 1]), 0.f);
    v.z = fmaxf(fmaf(v.z, ssc[cb + 2], ssh[cb + 2]), 0.f);
    v.w = fmaxf(fmaf(v.w, ssc[cb + 3], ssh[cb + 3]), 0.f);
    ((float4*)out)[idx] = v;
}

// ---------------- launch ----------------
extern "C" void kernel_launch(void* const* d_in, const int* in_sizes, int n_in,
                              void* d_out, int out_size) {
    const float* x      = (const float*)d_in[0];
    const void*  ei_sc  = d_in[1];
    const float* wsc    = (const float*)d_in[2];
    // d_in[3] = edge_index_fc (unused by the reference math)
    const float* wfc    = (const float*)d_in[4];
    const float* alpha  = (const float*)d_in[5];
    const float* W1     = (const float*)d_in[6];
    const float* b1     = (const float*)d_in[7];
    const float* W2     = (const float*)d_in[8];
    const float* b2     = (const float*)d_in[9];
    const float* gamma1 = (const float*)d_in[10];
    const float* beta1  = (const float*)d_in[11];
    const float* gamma2 = (const float*)d_in[12];
    const float* beta2  = (const float*)d_in[13];
    float*       out    = (float*)d_out;

    const int TB = 256;
    float* d_sum1; cudaGetSymbolAddress((void**)&d_sum1, g_sum1);
    float* d_sq1;  cudaGetSymbolAddress((void**)&d_sq1,  g_sq1);
    float* d_sum2; cudaGetSymbolAddress((void**)&d_sum2, g_sum2);
    float* d_sq2;  cudaGetSymbolAddress((void**)&d_sq2,  g_sq2);

    k_init<<<(NN + TB - 1) / TB, TB>>>((const int*)ei_sc);
    k_edge_prep<<<(NE + TB - 1) / TB, TB>>>(ei_sc, wsc, wfc, alpha);
    k_scan1<<<NB_SCAN, SCAN_B>>>();
    k_scan2<<<1, 128>>>();
    k_scan3<<<NB_SCAN, SCAN_B>>>();
    k_fill<<<(NE + NN + TB - 1) / TB, TB>>>();
    k_gemm1<<<(NN + 31) / 32, TB>>>(x, W1);
    k_agg<<<NN / 8, TB>>>(b1, d_sum1, d_sq1);
    k_gemm2<<<(NN + 31) / 32, TB>>>(W2, gamma1, beta1);
    k_agg<<<NN / 8, TB>>>(b2, d_sum2, d_sq2);
    k_final<<<(NN * (DH / 4) + TB - 1) / TB, TB>>>(gamma2, beta2, out);
}

// round 5
// speedup vs baseline: 1.5103x; 1.0322x over previous
#include <cuda_runtime.h>
#include <cuda_fp16.h>

#define NN 50000
#define NE 1600000
#define TOT (NE + NN)
#define DIN 128
#define DH  64
#define SCAN_B 512
#define NB_SCAN 98   // ceil(NN/512)
#define BN_EPS 1e-5f

// ---------------- scratch ----------------
__device__ int   g_src[NE];
__device__ int   g_dst[NE];
__device__ int   g_rank[NE];
__device__ float g_w[NE];
__device__ float g_deg[NN];
__device__ float g_dinv[NN];
__device__ int   g_cnt[NN];
__device__ int   g_rowstart[NN];     // pre-offset (within scan block)
__device__ int   g_bsum[NB_SCAN];
__device__ __align__(16) int2    g_cv[TOT];          // (col, dinv[src]*w as bits)
__device__ __align__(16) __half2 g_h[NN * (DH / 2)]; // fp16 features for gather
__device__ __align__(16) float   g_agg[NN * DH];     // fp32 aggregation output
__device__ float g_sum1[DH], g_sq1[DH], g_sum2[DH], g_sq2[DH];
__device__ int   g_is64 = 1;   // probe only ever clears it (stable across replays)

// ---------------- f32x2 packed-FMA helpers (sm_10x FFMA2; PTX-only) ----------------
__device__ __forceinline__ unsigned long long bcast2(float x) {
    unsigned long long r; asm("mov.b64 %0, {%1,%1};" : "=l"(r) : "f"(x)); return r;
}
__device__ __forceinline__ void fma2(unsigned long long& d, unsigned long long a, unsigned long long b) {
    asm("fma.rn.f32x2 %0, %1, %2, %0;" : "+l"(d) : "l"(a), "l"(b));
}
__device__ __forceinline__ float2 unpack2(unsigned long long v) {
    float2 f; asm("mov.b64 {%0,%1}, %2;" : "=f"(f.x), "=f"(f.y) : "l"(v)); return f;
}

// ---------------- init + dtype probe ----------------
__global__ void k_init(const int* __restrict__ ei32) {
    int i = blockIdx.x * blockDim.x + threadIdx.x;
    if (i < NN) { g_deg[i] = 1.0f; g_cnt[i] = 1; }     // self-loop: weight 1, rank 0
    if (i < DH) { g_sum1[i] = 0.f; g_sq1[i] = 0.f; g_sum2[i] = 0.f; g_sq2[i] = 0.f; }
    if (blockIdx.x == 0 && threadIdx.x < 256) {
        int k = threadIdx.x * (NE / 256);
        if (ei32[2 * k + 1] != 0) g_is64 = 0;          // int64 LE high word is 0
    }
}

// ---------------- edge prep: mix weights, degree, counts(+rank) ----------------
__global__ void k_edge_prep(const void* __restrict__ ei,
                            const float* __restrict__ wsc,
                            const float* __restrict__ wfc,
                            const float* __restrict__ alpha) {
    int e = blockIdx.x * blockDim.x + threadIdx.x;
    if (e >= NE) return;
    float a = 1.f / (1.f + __expf(-__ldg(alpha)));
    int s, d;
    if (g_is64) {
        const long long* p = (const long long*)ei;
        s = (int)__ldg(&p[e]);
        d = (int)__ldg(&p[NE + e]);
    } else {
        const int* p = (const int*)ei;
        s = __ldg(&p[e]);
        d = __ldg(&p[NE + e]);
    }
    s = min(max(s, 0), NN - 1);
    d = min(max(d, 0), NN - 1);
    float w = a * __ldg(&wsc[e]) + (1.f - a) * __ldg(&wfc[e]);
    g_src[e] = s; g_dst[e] = d; g_w[e] = w;
    atomicAdd(&g_deg[d], w);
    g_rank[e] = atomicAdd(&g_cnt[d], 1);   // rank within destination row (>=1; 0 = self loop)
}

// ---------------- scan pass 1: per-block exclusive scan of counts; fused dinv ----------------
__global__ void k_scan1() {
    __shared__ int s[SCAN_B];
    int t = threadIdx.x;
    int i = blockIdx.x * SCAN_B + t;
    int v = (i < NN) ? g_cnt[i] : 0;
    s[t] = v; __syncthreads();
    for (int off = 1; off < SCAN_B; off <<= 1) {
        int u = (t >= off) ? s[t - off] : 0;
        __syncthreads();
        s[t] += u; __syncthreads();
    }
    if (i < NN) {
        g_rowstart[i] = s[t] - v;                 // exclusive, pre-offset
        g_dinv[i] = rsqrtf(g_deg[i]);             // deg >= 1 (self loop)
    }
    if (t == SCAN_B - 1) g_bsum[blockIdx.x] = s[t];
}
// ---------------- scan pass 2: exclusive scan of block sums ----------------
__global__ void k_scan2() {
    __shared__ int s[128];
    int t = threadIdx.x;
    int v = (t < NB_SCAN) ? g_bsum[t] : 0;
    s[t] = v; __syncthreads();
    for (int off = 1; off < 128; off <<= 1) {
        int u = (t >= off) ? s[t - off] : 0;
        __syncthreads();
        s[t] += u; __syncthreads();
    }
    if (t < NB_SCAN) g_bsum[t] = s[t] - v;
}

__device__ __forceinline__ int rowbeg(int i) { return g_rowstart[i] + g_bsum[i >> 9]; }

// ---------------- CSR fill: atomic-free scatter; value = dinv[src]*w ----------------
__global__ void k_fill() {
    int e = blockIdx.x * blockDim.x + threadIdx.x;
    if (e < NE) {
        int d = g_dst[e], s = g_src[e];
        int p = rowbeg(d) + g_rank[e];
        float nv = g_dinv[s] * g_w[e];
        g_cv[p] = make_int2(s, __float_as_int(nv));
    } else if (e < NE + NN) {
        int i = e - NE;
        g_cv[rowbeg(i)] = make_int2(i, __float_as_int(g_dinv[i]));   // self loop, rank 0
    }
}

// ---------------- GEMM1: g_h(fp16) = x[N,128] @ W1[128,64] ----------------
__global__ void __launch_bounds__(256) k_gemm1(const float* __restrict__ x,
                                               const float* __restrict__ W1) {
    __shared__ __align__(16) float sW[DIN * DH];      // 32 KB
    for (int i = threadIdx.x; i < DIN * DH; i += 256) sW[i] = W1[i];
    __syncthreads();
    int warp = threadIdx.x >> 5, lane = threadIdx.x & 31;
    int nbase = blockIdx.x * 32 + warp * 4;
    if (nbase >= NN) return;
    int n0 = nbase, n1 = min(nbase + 1, NN - 1), n2 = min(nbase + 2, NN - 1), n3 = min(nbase + 3, NN - 1);
    const float4* x0 = (const float4*)(x + (size_t)n0 * DIN);
    const float4* x1 = (const float4*)(x + (size_t)n1 * DIN);
    const float4* x2 = (const float4*)(x + (size_t)n2 * DIN);
    const float4* x3 = (const float4*)(x + (size_t)n3 * DIN);
    unsigned long long a0 = 0ULL, a1 = 0ULL, a2 = 0ULL, a3 = 0ULL;
    #pragma unroll
    for (int kk = 0; kk < DIN / 4; ++kk) {
        float ra[4], rb[4], rc[4], rd[4];
        *(float4*)ra = __ldg(x0 + kk);
        *(float4*)rb = __ldg(x1 + kk);
        *(float4*)rc = __ldg(x2 + kk);
        *(float4*)rd = __ldg(x3 + kk);
        #pragma unroll
        for (int u = 0; u < 4; ++u) {
            unsigned long long w = *(const unsigned long long*)&sW[(4 * kk + u) * DH + 2 * lane];
            fma2(a0, bcast2(ra[u]), w);
            fma2(a1, bcast2(rb[u]), w);
            fma2(a2, bcast2(rc[u]), w);
            fma2(a3, bcast2(rd[u]), w);
        }
    }
    g_h[(size_t)n0 * 32 + lane] = __float22half2_rn(unpack2(a0));
    if (nbase + 1 < NN) g_h[(size_t)n1 * 32 + lane] = __float22half2_rn(unpack2(a1));
    if (nbase + 2 < NN) g_h[(size_t)n2 * 32 + lane] = __float22half2_rn(unpack2(a2));
    if (nbase + 3 < NN) g_h[(size_t)n3 * 32 + lane] = __float22half2_rn(unpack2(a3));
}

// ---------------- CSR gather agg (row scaled by dinv[dst]) + bias, fused column stats ----------------
__global__ void __launch_bounds__(256) k_agg(const float* __restrict__ bias,
                                             float* __restrict__ gsum,
                                             float* __restrict__ gsq) {
    __shared__ float s_sum[DH], s_sq[DH];
    if (threadIdx.x < DH) { s_sum[threadIdx.x] = 0.f; s_sq[threadIdx.x] = 0.f; }
    __syncthreads();
    int gw = blockIdx.x * 8 + (threadIdx.x >> 5);
    int lane = threadIdx.x & 31;
    int beg = rowbeg(gw);
    int end = (gw == NN - 1) ? TOT : rowbeg(gw + 1);
    const __half2* hp = g_h;
    float2 acc = {0.f, 0.f};
    int j = beg;
    for (; j + 4 <= end; j += 4) {
        int2 c0 = g_cv[j], c1 = g_cv[j + 1], c2 = g_cv[j + 2], c3 = g_cv[j + 3];
        float2 h0 = __half22float2(__ldg(&hp[(size_t)c0.x * 32 + lane]));
        float2 h1 = __half22float2(__ldg(&hp[(size_t)c1.x * 32 + lane]));
        float2 h2 = __half22float2(__ldg(&hp[(size_t)c2.x * 32 + lane]));
        float2 h3 = __half22float2(__ldg(&hp[(size_t)c3.x * 32 + lane]));
        float v0 = __int_as_float(c0.y), v1 = __int_as_float(c1.y);
        float v2 = __int_as_float(c2.y), v3 = __int_as_float(c3.y);
        acc.x += v0 * h0.x; acc.y += v0 * h0.y;
        acc.x += v1 * h1.x; acc.y += v1 * h1.y;
        acc.x += v2 * h2.x; acc.y += v2 * h2.y;
        acc.x += v3 * h3.x; acc.y += v3 * h3.y;
    }
    for (; j < end; ++j) {
        int2 c = g_cv[j];
        float2 hv = __half22float2(__ldg(&hp[(size_t)c.x * 32 + lane]));
        float v = __int_as_float(c.y);
        acc.x += v * hv.x; acc.y += v * hv.y;
    }
    float di = g_dinv[gw];
    acc.x = acc.x * di + __ldg(&bias[2 * lane]);
    acc.y = acc.y * di + __ldg(&bias[2 * lane + 1]);
    *(float2*)&g_agg[(size_t)gw * DH + 2 * lane] = acc;
    atomicAdd(&s_sum[2 * lane],     acc.x);
    atomicAdd(&s_sum[2 * lane + 1], acc.y);
    atomicAdd(&s_sq[2 * lane],      acc.x * acc.x);
    atomicAdd(&s_sq[2 * lane + 1],  acc.y * acc.y);
    __syncthreads();
    if (threadIdx.x < DH) {
        atomicAdd(&gsum[threadIdx.x], s_sum[threadIdx.x]);
        atomicAdd(&gsq[threadIdx.x],  s_sq[threadIdx.x]);
    }
}

// ---------------- GEMM2: g_h(fp16) = relu(bn(g_agg)) @ W2[64,64]; BN params from stats ----------------
__global__ void __launch_bounds__(256) k_gemm2(const float* __restrict__ W2,
                                               const float* __restrict__ gamma,
                                               const float* __restrict__ beta) {
    __shared__ __align__(16) float sW[DH * DH];
    __shared__ __align__(16) float ssc[DH], ssh[DH];
    for (int i = threadIdx.x; i < DH * DH; i += 256) sW[i] = W2[i];
    if (threadIdx.x < DH) {
        int c = threadIdx.x;
        float mean = g_sum1[c] * (1.f / NN);
        float var  = g_sq1[c] * (1.f / NN) - mean * mean;
        float inv  = rsqrtf(var + BN_EPS);
        float sc   = __ldg(&gamma[c]) * inv;
        ssc[c] = sc;
        ssh[c] = __ldg(&beta[c]) - mean * sc;
    }
    __syncthreads();
    int warp = threadIdx.x >> 5, lane = threadIdx.x & 31;
    int nbase = blockIdx.x * 32 + warp * 4;
    if (nbase >= NN) return;
    int n0 = nbase, n1 = min(nbase + 1, NN - 1), n2 = min(nbase + 2, NN - 1), n3 = min(nbase + 3, NN - 1);
    const float4* x0 = (const float4*)(g_agg + (size_t)n0 * DH);
    const float4* x1 = (const float4*)(g_agg + (size_t)n1 * DH);
    const float4* x2 = (const float4*)(g_agg + (size_t)n2 * DH);
    const float4* x3 = (const float4*)(g_agg + (size_t)n3 * DH);
    unsigned long long a0 = 0ULL, a1 = 0ULL, a2 = 0ULL, a3 = 0ULL;
    #pragma unroll
    for (int kk = 0; kk < DH / 4; ++kk) {
        float ra[4], rb[4], rc[4], rd[4];
        *(float4*)ra = __ldg(x0 + kk);
        *(float4*)rb = __ldg(x1 + kk);
        *(float4*)rc = __ldg(x2 + kk);
        *(float4*)rd = __ldg(x3 + kk);
        float scs[4], shs[4];
        *(float4*)scs = *(float4*)&ssc[4 * kk];
        *(float4*)shs = *(float4*)&ssh[4 * kk];
        #pragma unroll
        for (int u = 0; u < 4; ++u) {
            unsigned long long w = *(const unsigned long long*)&sW[(4 * kk + u) * DH + 2 * lane];
            float va = fmaxf(fmaf(ra[u], scs[u], shs[u]), 0.f);
            float vb = fmaxf(fmaf(rb[u], scs[u], shs[u]), 0.f);
            float vc = fmaxf(fmaf(rc[u], scs[u], shs[u]), 0.f);
            float vd = fmaxf(fmaf(rd[u], scs[u], shs[u]), 0.f);
            fma2(a0, bcast2(va), w);
            fma2(a1, bcast2(vb), w);
            fma2(a2, bcast2(vc), w);
            fma2(a3, bcast2(vd), w);
        }
    }
    g_h[(size_t)n0 * 32 + lane] = __float22half2_rn(unpack2(a0));
    if (nbase + 1 < NN) g_h[(size_t)n1 * 32 + lane] = __float22half2_rn(unpack2(a1));
    if (nbase + 2 < NN) g_h[(size_t)n2 * 32 + lane] = __float22half2_rn(unpack2(a2));
    if (nbase + 3 < NN) g_h[(size_t)n3 * 32 + lane] = __float22half2_rn(unpack2(a3));
}

// ---------------- final: out = relu(bn(g_agg)); BN params from stats ----------------
__global__ void __launch_bounds__(256) k_final(const float* __restrict__ gamma,
                                               const float* __restrict__ beta,
                                               float* __restrict__ out) {
    __shared__ float ssc[DH], ssh[DH];
    if (threadIdx.x < DH) {
        int c = threadIdx.x;
        float mean = g_sum2[c] * (1.f / NN);
        float var  = g_sq2[c] * (1.f / NN) - mean * mean;
        float inv  = rsqrtf(var + BN_EPS);
        float sc   = __ldg(&gamma[c]) * inv;
        ssc[c] = sc;
        ssh[c] = __ldg(&beta[c]) - mean * sc;
    }
    __syncthreads();
    int idx = blockIdx.x * blockDim.x + threadIdx.x;   // over NN*16 float4s
    if (idx >= NN * (DH / 4)) return;
    float4 v = ((const float4*)g_agg)[idx];
    int cb = (idx & (DH / 4 - 1)) * 4;
    v.x = fmaxf(fmaf(v.x, ssc[cb + 0], ssh[cb + 0]), 0.f);
    v.y = fmaxf(fmaf(v.y, ssc[cb + 1], ssh[cb + 1]), 0.f);
    v.z = fmaxf(fmaf(v.z, ssc[cb + 2], ssh[cb + 2]), 0.f);
    v.w = fmaxf(fmaf(v.w, ssc[cb + 3], ssh[cb + 3]), 0.f);
    ((float4*)out)[idx] = v;
}

// ---------------- launch ----------------
extern "C" void kernel_launch(void* const* d_in, const int* in_sizes, int n_in,
                              void* d_out, int out_size) {
    const float* x      = (const float*)d_in[0];
    const void*  ei_sc  = d_in[1];
    const float* wsc    = (const float*)d_in[2];
    // d_in[3] = edge_index_fc (unused by the reference math)
    const float* wfc    = (const float*)d_in[4];
    const float* alpha  = (const float*)d_in[5];
    const float* W1     = (const float*)d_in[6];
    const float* b1     = (const float*)d_in[7];
    const float* W2     = (const float*)d_in[8];
    const float* b2     = (const float*)d_in[9];
    const float* gamma1 = (const float*)d_in[10];
    const float* beta1  = (const float*)d_in[11];
    const float* gamma2 = (const float*)d_in[12];
    const float* beta2  = (const float*)d_in[13];
    float*       out    = (float*)d_out;

    const int TB = 256;
    float* d_sum1; cudaGetSymbolAddress((void**)&d_sum1, g_sum1);
    float* d_sq1;  cudaGetSymbolAddress((void**)&d_sq1,  g_sq1);
    float* d_sum2; cudaGetSymbolAddress((void**)&d_sum2, g_sum2);
    float* d_sq2;  cudaGetSymbolAddress((void**)&d_sq2,  g_sq2);

    // side stream for gemm1 overlap (created once; streams/events are not device memory)
    static cudaStream_t s2 = nullptr;
    static cudaEvent_t ev_fork = nullptr, ev_join = nullptr;
    if (!s2) {
        cudaStreamCreateWithFlags(&s2, cudaStreamNonBlocking);
        cudaEventCreateWithFlags(&ev_fork, cudaEventDisableTiming);
        cudaEventCreateWithFlags(&ev_join, cudaEventDisableTiming);
    }

    k_init<<<(NN + TB - 1) / TB, TB>>>((const int*)ei_sc);
    // fork: gemm1 depends only on x/W1; overlap with edge preprocessing
    cudaEventRecord(ev_fork, 0);
    cudaStreamWaitEvent(s2, ev_fork, 0);
    k_gemm1<<<(NN + 31) / 32, TB, 0, s2>>>(x, W1);
    cudaEventRecord(ev_join, s2);

    k_edge_prep<<<(NE + TB - 1) / TB, TB>>>(ei_sc, wsc, wfc, alpha);
    k_scan1<<<NB_SCAN, SCAN_B>>>();
    k_scan2<<<1, 128>>>();
    k_fill<<<(NE + NN + TB - 1) / TB, TB>>>();

    cudaStreamWaitEvent(0, ev_join, 0);   // join before consuming g_h
    k_agg<<<NN / 8, TB>>>(b1, d_sum1, d_sq1);
    k_gemm2<<<(NN + 31) / 32, TB>>>(W2, gamma1, beta1);
    k_agg<<<NN / 8, TB>>>(b2, d_sum2, d_sq2);
    k_final<<<(NN * (DH / 4) + TB - 1) / TB, TB>>>(gamma2, beta2, out);
}

// round 6
// speedup vs baseline: 1.6438x; 1.0884x over previous
#include <cuda_runtime.h>
#include <cuda_fp16.h>

#define NN 50000
#define NE 1600000
#define TOT (NE + NN)
#define DIN 128
#define DH  64
#define SCAN_B 512
#define NB_SCAN 98   // ceil(NN/512)
#define BN_EPS 1e-5f
#define FXS 16777216.0f   // 2^24 fixed-point scale for degree accumulation

// ---------------- scratch ----------------
__device__ int                g_src[NE];
__device__ unsigned int       g_dr[NE];        // (dst << 16) | rank
__device__ float              g_w[NE];
__device__ unsigned long long g_dc[NN];        // (count << 40) | sum(w * 2^24)
__device__ float              g_dinv[NN];
__device__ int                g_rowstart[NN];  // pre-offset (within scan block)
__device__ int                g_bsum[NB_SCAN];
__device__ int                g_scanctr;       // last-block counter (reset by last block)
__device__ __align__(16) int2    g_cv[TOT];          // (col, dinv[src]*w as bits)
__device__ __align__(16) __half2 g_h[NN * (DH / 2)]; // fp16 features for gather
__device__ __align__(16) float   g_agg[NN * DH];     // fp32 aggregation output
__device__ float g_sum1[DH], g_sq1[DH], g_sum2[DH], g_sq2[DH];
__device__ int   g_is64 = 1;   // probe only ever clears it (stable across replays)

// ---------------- f32x2 packed-FMA helpers (sm_10x FFMA2; PTX-only) ----------------
__device__ __forceinline__ unsigned long long bcast2(float x) {
    unsigned long long r; asm("mov.b64 %0, {%1,%1};" : "=l"(r) : "f"(x)); return r;
}
__device__ __forceinline__ void fma2(unsigned long long& d, unsigned long long a, unsigned long long b) {
    asm("fma.rn.f32x2 %0, %1, %2, %0;" : "+l"(d) : "l"(a), "l"(b));
}
__device__ __forceinline__ float2 unpack2(unsigned long long v) {
    float2 f; asm("mov.b64 {%0,%1}, %2;" : "=f"(f.x), "=f"(f.y) : "l"(v)); return f;
}

// ---------------- init + dtype probe ----------------
__global__ void k_init(const int* __restrict__ ei32) {
    int i = blockIdx.x * blockDim.x + threadIdx.x;
    if (i < NN) g_dc[i] = (1ull << 40);   // self loop: count=1 (rank 0 reserved), wsum=0
    if (i < DH) { g_sum1[i] = 0.f; g_sq1[i] = 0.f; g_sum2[i] = 0.f; g_sq2[i] = 0.f; }
    if (blockIdx.x == 0 && threadIdx.x < 256) {
        int k = threadIdx.x * (NE / 256);
        if (ei32[2 * k + 1] != 0) g_is64 = 0;   // int64 LE high word is 0
    }
}

// ---------------- edge prep: mix weights; ONE packed 64-bit atomic per edge ----------------
__global__ void k_edge_prep(const void* __restrict__ ei,
                            const float* __restrict__ wsc,
                            const float* __restrict__ wfc,
                            const float* __restrict__ alpha) {
    int e = blockIdx.x * blockDim.x + threadIdx.x;
    if (e >= NE) return;
    float a = 1.f / (1.f + __expf(-__ldg(alpha)));
    int s, d;
    if (g_is64) {
        const long long* p = (const long long*)ei;
        s = (int)__ldg(&p[e]);
        d = (int)__ldg(&p[NE + e]);
    } else {
        const int* p = (const int*)ei;
        s = __ldg(&p[e]);
        d = __ldg(&p[NE + e]);
    }
    s = min(max(s, 0), NN - 1);
    d = min(max(d, 0), NN - 1);
    float w = a * __ldg(&wsc[e]) + (1.f - a) * __ldg(&wfc[e]);
    unsigned long long wfx = (unsigned long long)(w * FXS + 0.5f);
    unsigned long long old = atomicAdd(&g_dc[d], (1ull << 40) | wfx);
    unsigned int rank = (unsigned int)(old >> 40);
    rank = min(rank, 65535u);
    g_src[e] = s;
    g_w[e]   = w;
    g_dr[e]  = ((unsigned int)d << 16) | rank;
}

// ---------------- fused scan: per-block scan + last-block scans block sums; fused dinv ----------------
__global__ void __launch_bounds__(SCAN_B) k_scan() {
    __shared__ int s[SCAN_B];
    __shared__ int is_last;
    int t = threadIdx.x;
    int i = blockIdx.x * SCAN_B + t;
    int v = 0;
    float deg = 1.0f;
    if (i < NN) {
        unsigned long long dc = g_dc[i];
        v = (int)(dc >> 40);                               // count (>=1)
        deg = 1.0f + (float)(dc & ((1ull << 40) - 1)) * (1.0f / FXS);
    }
    s[t] = v; __syncthreads();
    for (int off = 1; off < SCAN_B; off <<= 1) {
        int u = (t >= off) ? s[t - off] : 0;
        __syncthreads();
        s[t] += u; __syncthreads();
    }
    if (i < NN) {
        g_rowstart[i] = s[t] - v;                          // exclusive, pre-offset
        g_dinv[i] = rsqrtf(deg);
    }
    if (t == SCAN_B - 1) g_bsum[blockIdx.x] = s[t];
    // last block scans the 98 block sums
    __threadfence();
    if (t == 0) is_last = (atomicAdd(&g_scanctr, 1) == NB_SCAN - 1);
    __syncthreads();
    if (is_last) {
        if (t == 0) g_scanctr = 0;                         // reset for next replay
        if (t < 128) {
            __shared__ int bs[128];
            int bv = (t < NB_SCAN) ? g_bsum[t] : 0;
            bs[t] = bv; __syncwarp();
            __syncthreads();
            for (int off = 1; off < 128; off <<= 1) {
                int u = (t >= off) ? bs[t - off] : 0;
                __syncthreads();
                bs[t] += u; __syncthreads();
            }
            if (t < NB_SCAN) g_bsum[t] = bs[t] - bv;       // exclusive block offsets
        }
    }
}

__device__ __forceinline__ int rowbeg(int i) { return g_rowstart[i] + g_bsum[i >> 9]; }

// ---------------- CSR fill: atomic-free scatter; value = dinv[src]*w ----------------
__global__ void k_fill() {
    int e = blockIdx.x * blockDim.x + threadIdx.x;
    if (e < NE) {
        unsigned int dr = g_dr[e];
        int d = (int)(dr >> 16);
        int rank = (int)(dr & 0xffffu);
        int s = g_src[e];
        int p = min(rowbeg(d) + rank, TOT - 1);
        float nv = g_dinv[s] * g_w[e];
        g_cv[p] = make_int2(s, __float_as_int(nv));
    } else if (e < NE + NN) {
        int i = e - NE;
        g_cv[rowbeg(i)] = make_int2(i, __float_as_int(g_dinv[i]));   // self loop, rank 0
    }
}

// ---------------- GEMM1: g_h(fp16) = x[N,128] @ W1[128,64] ----------------
__global__ void __launch_bounds__(256) k_gemm1(const float* __restrict__ x,
                                               const float* __restrict__ W1) {
    __shared__ __align__(16) float sW[DIN * DH];      // 32 KB
    for (int i = threadIdx.x; i < DIN * DH; i += 256) sW[i] = W1[i];
    __syncthreads();
    int warp = threadIdx.x >> 5, lane = threadIdx.x & 31;
    int nbase = blockIdx.x * 32 + warp * 4;
    if (nbase >= NN) return;
    int n0 = nbase, n1 = min(nbase + 1, NN - 1), n2 = min(nbase + 2, NN - 1), n3 = min(nbase + 3, NN - 1);
    const float4* x0 = (const float4*)(x + (size_t)n0 * DIN);
    const float4* x1 = (const float4*)(x + (size_t)n1 * DIN);
    const float4* x2 = (const float4*)(x + (size_t)n2 * DIN);
    const float4* x3 = (const float4*)(x + (size_t)n3 * DIN);
    unsigned long long a0 = 0ULL, a1 = 0ULL, a2 = 0ULL, a3 = 0ULL;
    #pragma unroll
    for (int kk = 0; kk < DIN / 4; ++kk) {
        float ra[4], rb[4], rc[4], rd[4];
        *(float4*)ra = __ldg(x0 + kk);
        *(float4*)rb = __ldg(x1 + kk);
        *(float4*)rc = __ldg(x2 + kk);
        *(float4*)rd = __ldg(x3 + kk);
        #pragma unroll
        for (int u = 0; u < 4; ++u) {
            unsigned long long w = *(const unsigned long long*)&sW[(4 * kk + u) * DH + 2 * lane];
            fma2(a0, bcast2(ra[u]), w);
            fma2(a1, bcast2(rb[u]), w);
            fma2(a2, bcast2(rc[u]), w);
            fma2(a3, bcast2(rd[u]), w);
        }
    }
    g_h[(size_t)n0 * 32 + lane] = __float22half2_rn(unpack2(a0));
    if (nbase + 1 < NN) g_h[(size_t)n1 * 32 + lane] = __float22half2_rn(unpack2(a1));
    if (nbase + 2 < NN) g_h[(size_t)n2 * 32 + lane] = __float22half2_rn(unpack2(a2));
    if (nbase + 3 < NN) g_h[(size_t)n3 * 32 + lane] = __float22half2_rn(unpack2(a3));
}

// ---------------- CSR gather agg (row scaled by dinv[dst]) + bias, fused column stats ----------------
__global__ void __launch_bounds__(256) k_agg(const float* __restrict__ bias,
                                             float* __restrict__ gsum,
                                             float* __restrict__ gsq) {
    __shared__ float s_sum[DH], s_sq[DH];
    if (threadIdx.x < DH) { s_sum[threadIdx.x] = 0.f; s_sq[threadIdx.x] = 0.f; }
    __syncthreads();
    int gw = blockIdx.x * 8 + (threadIdx.x >> 5);
    int lane = threadIdx.x & 31;
    int beg = rowbeg(gw);
    int end = (gw == NN - 1) ? TOT : rowbeg(gw + 1);
    const __half2* hp = g_h;
    float2 acc = {0.f, 0.f};
    int j = beg;
    for (; j + 4 <= end; j += 4) {
        int2 c0 = g_cv[j], c1 = g_cv[j + 1], c2 = g_cv[j + 2], c3 = g_cv[j + 3];
        float2 h0 = __half22float2(__ldg(&hp[(size_t)c0.x * 32 + lane]));
        float2 h1 = __half22float2(__ldg(&hp[(size_t)c1.x * 32 + lane]));
        float2 h2 = __half22float2(__ldg(&hp[(size_t)c2.x * 32 + lane]));
        float2 h3 = __half22float2(__ldg(&hp[(size_t)c3.x * 32 + lane]));
        float v0 = __int_as_float(c0.y), v1 = __int_as_float(c1.y);
        float v2 = __int_as_float(c2.y), v3 = __int_as_float(c3.y);
        acc.x += v0 * h0.x; acc.y += v0 * h0.y;
        acc.x += v1 * h1.x; acc.y += v1 * h1.y;
        acc.x += v2 * h2.x; acc.y += v2 * h2.y;
        acc.x += v3 * h3.x; acc.y += v3 * h3.y;
    }
    for (; j < end; ++j) {
        int2 c = g_cv[j];
        float2 hv = __half22float2(__ldg(&hp[(size_t)c.x * 32 + lane]));
        float v = __int_as_float(c.y);
        acc.x += v * hv.x; acc.y += v * hv.y;
    }
    float di = g_dinv[gw];
    acc.x = acc.x * di + __ldg(&bias[2 * lane]);
    acc.y = acc.y * di + __ldg(&bias[2 * lane + 1]);
    *(float2*)&g_agg[(size_t)gw * DH + 2 * lane] = acc;
    atomicAdd(&s_sum[2 * lane],     acc.x);
    atomicAdd(&s_sum[2 * lane + 1], acc.y);
    atomicAdd(&s_sq[2 * lane],      acc.x * acc.x);
    atomicAdd(&s_sq[2 * lane + 1],  acc.y * acc.y);
    __syncthreads();
    if (threadIdx.x < DH) {
        atomicAdd(&gsum[threadIdx.x], s_sum[threadIdx.x]);
        atomicAdd(&gsq[threadIdx.x],  s_sq[threadIdx.x]);
    }
}

// ---------------- GEMM2: g_h(fp16) = relu(bn(g_agg)) @ W2[64,64]; BN params from stats ----------------
__global__ void __launch_bounds__(256) k_gemm2(const float* __restrict__ W2,
                                               const float* __restrict__ gamma,
                                               const float* __restrict__ beta) {
    __shared__ __align__(16) float sW[DH * DH];
    __shared__ __align__(16) float ssc[DH], ssh[DH];
    for (int i = threadIdx.x; i < DH * DH; i += 256) sW[i] = W2[i];
    if (threadIdx.x < DH) {
        int c = threadIdx.x;
        float mean = g_sum1[c] * (1.f / NN);
        float var  = g_sq1[c] * (1.f / NN) - mean * mean;
        float inv  = rsqrtf(var + BN_EPS);
        float sc   = __ldg(&gamma[c]) * inv;
        ssc[c] = sc;
        ssh[c] = __ldg(&beta[c]) - mean * sc;
    }
    __syncthreads();
    int warp = threadIdx.x >> 5, lane = threadIdx.x & 31;
    int nbase = blockIdx.x * 32 + warp * 4;
    if (nbase >= NN) return;
    int n0 = nbase, n1 = min(nbase + 1, NN - 1), n2 = min(nbase + 2, NN - 1), n3 = min(nbase + 3, NN - 1);
    const float4* x0 = (const float4*)(g_agg + (size_t)n0 * DH);
    const float4* x1 = (const float4*)(g_agg + (size_t)n1 * DH);
    const float4* x2 = (const float4*)(g_agg + (size_t)n2 * DH);
    const float4* x3 = (const float4*)(g_agg + (size_t)n3 * DH);
    unsigned long long a0 = 0ULL, a1 = 0ULL, a2 = 0ULL, a3 = 0ULL;
    #pragma unroll
    for (int kk = 0; kk < DH / 4; ++kk) {
        float ra[4], rb[4], rc[4], rd[4];
        *(float4*)ra = __ldg(x0 + kk);
        *(float4*)rb = __ldg(x1 + kk);
        *(float4*)rc = __ldg(x2 + kk);
        *(float4*)rd = __ldg(x3 + kk);
        float scs[4], shs[4];
        *(float4*)scs = *(float4*)&ssc[4 * kk];
        *(float4*)shs = *(float4*)&ssh[4 * kk];
        #pragma unroll
        for (int u = 0; u < 4; ++u) {
            unsigned long long w = *(const unsigned long long*)&sW[(4 * kk + u) * DH + 2 * lane];
            float va = fmaxf(fmaf(ra[u], scs[u], shs[u]), 0.f);
            float vb = fmaxf(fmaf(rb[u], scs[u], shs[u]), 0.f);
            float vc = fmaxf(fmaf(rc[u], scs[u], shs[u]), 0.f);
            float vd = fmaxf(fmaf(rd[u], scs[u], shs[u]), 0.f);
            fma2(a0, bcast2(va), w);
            fma2(a1, bcast2(vb), w);
            fma2(a2, bcast2(vc), w);
            fma2(a3, bcast2(vd), w);
        }
    }
    g_h[(size_t)n0 * 32 + lane] = __float22half2_rn(unpack2(a0));
    if (nbase + 1 < NN) g_h[(size_t)n1 * 32 + lane] = __float22half2_rn(unpack2(a1));
    if (nbase + 2 < NN) g_h[(size_t)n2 * 32 + lane] = __float22half2_rn(unpack2(a2));
    if (nbase + 3 < NN) g_h[(size_t)n3 * 32 + lane] = __float22half2_rn(unpack2(a3));
}

// ---------------- final: out = relu(bn(g_agg)); BN params from stats ----------------
__global__ void __launch_bounds__(256) k_final(const float* __restrict__ gamma,
                                               const float* __restrict__ beta,
                                               float* __restrict__ out) {
    __shared__ float ssc[DH], ssh[DH];
    if (threadIdx.x < DH) {
        int c = threadIdx.x;
        float mean = g_sum2[c] * (1.f / NN);
        float var  = g_sq2[c] * (1.f / NN) - mean * mean;
        float inv  = rsqrtf(var + BN_EPS);
        float sc   = __ldg(&gamma[c]) * inv;
        ssc[c] = sc;
        ssh[c] = __ldg(&beta[c]) - mean * sc;
    }
    __syncthreads();
    int idx = blockIdx.x * blockDim.x + threadIdx.x;   // over NN*16 float4s
    if (idx >= NN * (DH / 4)) return;
    float4 v = ((const float4*)g_agg)[idx];
    int cb = (idx & (DH / 4 - 1)) * 4;
    v.x = fmaxf(fmaf(v.x, ssc[cb + 0], ssh[cb + 0]), 0.f);
    v.y = fmaxf(fmaf(v.y, ssc[cb + 1], ssh[cb + 1]), 0.f);
    v.z = fmaxf(fmaf(v.z, ssc[cb + 2], ssh[cb + 2]), 0.f);
    v.w = fmaxf(fmaf(v.w, ssc[cb + 3], ssh[cb + 3]), 0.f);
    ((float4*)out)[idx] = v;
}

// ---------------- launch ----------------
extern "C" void kernel_launch(void* const* d_in, const int* in_sizes, int n_in,
                              void* d_out, int out_size) {
    const float* x      = (const float*)d_in[0];
    const void*  ei_sc  = d_in[1];
    const float* wsc    = (const float*)d_in[2];
    // d_in[3] = edge_index_fc (unused by the reference math)
    const float* wfc    = (const float*)d_in[4];
    const float* alpha  = (const float*)d_in[5];
    const float* W1     = (const float*)d_in[6];
    const float* b1     = (const float*)d_in[7];
    const float* W2     = (const float*)d_in[8];
    const float* b2     = (const float*)d_in[9];
    const float* gamma1 = (const float*)d_in[10];
    const float* beta1  = (const float*)d_in[11];
    const float* gamma2 = (const float*)d_in[12];
    const float* beta2  = (const float*)d_in[13];
    float*       out    = (float*)d_out;

    const int TB = 256;
    float* d_sum1; cudaGetSymbolAddress((void**)&d_sum1, g_sum1);
    float* d_sq1;  cudaGetSymbolAddress((void**)&d_sq1,  g_sq1);
    float* d_sum2; cudaGetSymbolAddress((void**)&d_sum2, g_sum2);
    float* d_sq2;  cudaGetSymbolAddress((void**)&d_sq2,  g_sq2);

    static cudaStream_t s2 = nullptr;
    static cudaEvent_t ev_fork = nullptr, ev_join = nullptr;
    if (!s2) {
        cudaStreamCreateWithFlags(&s2, cudaStreamNonBlocking);
        cudaEventCreateWithFlags(&ev_fork, cudaEventDisableTiming);
        cudaEventCreateWithFlags(&ev_join, cudaEventDisableTiming);
    }

    k_init<<<(NN + TB - 1) / TB, TB>>>((const int*)ei_sc);
    // fork: gemm1 depends only on x/W1; overlap with edge preprocessing
    cudaEventRecord(ev_fork, 0);
    cudaStreamWaitEvent(s2, ev_fork, 0);
    k_gemm1<<<(NN + 31) / 32, TB, 0, s2>>>(x, W1);
    cudaEventRecord(ev_join, s2);

    k_edge_prep<<<(NE + TB - 1) / TB, TB>>>(ei_sc, wsc, wfc, alpha);
    k_scan<<<NB_SCAN, SCAN_B>>>();
    k_fill<<<(NE + NN + TB - 1) / TB, TB>>>();

    cudaStreamWaitEvent(0, ev_join, 0);   // join before consuming g_h
    k_agg<<<NN / 8, TB>>>(b1, d_sum1, d_sq1);
    k_gemm2<<<(NN + 31) / 32, TB>>>(W2, gamma1, beta1);
    k_agg<<<NN / 8, TB>>>(b2, d_sum2, d_sq2);
    k_final<<<(NN * (DH / 4) + TB - 1) / TB, TB>>>(gamma2, beta2, out);
}